// round 4
// baseline (speedup 1.0000x reference)
#include <cuda_runtime.h>
#include <math.h>
#include <stdint.h>

#define Kdim 256
#define Tdim 64
#define Ddim 64
#define Hdim 256
#define Jdim 2016                  // 64*63/2
#define KJ   (Kdim*Jdim)           // 516096
#define TJ   64                    // pairs per tile
#define TILES_PER_K 32             // ceil(2016/64) — last tile ragged (32 valid)
#define NTILES (Kdim*TILES_PER_K)  // 8192
#define HS_STRIDE 68               // padded word stride for H tile rows (64 m + 4 pad)
#define GRID_MAIN 148              // 1 persistent block per SM

// Scratch (device globals — no allocation allowed)
__device__ float g_P[Kdim*Tdim*Hdim];   // 16.8 MB: emb @ W1[:64] + b1
__device__ float g_Q[Kdim*Tdim*Hdim];   // 16.8 MB: emb @ W1[64:]
__device__ int2  g_pairs[Jdim];

// ---------------------------------------------------------------------------
// Kernel 1: P/Q precompute (+ pair table from block 0). 256 thr, 16 rows/blk.
// ---------------------------------------------------------------------------
__global__ void __launch_bounds__(256) pq_kernel(const float* __restrict__ emb,
                                                 const float* __restrict__ W1,
                                                 const float* __restrict__ b1) {
    if (blockIdx.x == 0 && threadIdx.x < Tdim - 1) {
        int i = threadIdx.x;
        int start = i * (Tdim - 1) - i * (i - 1) / 2;
        for (int j = i + 1; j < Tdim; j++) g_pairs[start++] = make_int2(i, j);
    }
    __shared__ float es[16][64];
    int row0 = blockIdx.x * 16;
    int tid = threadIdx.x;
#pragma unroll
    for (int q = 0; q < 4; q++) {
        int v = tid + q * 256;
        es[v >> 6][v & 63] = emb[row0 * 64 + v];
    }
    __syncthreads();
    int c = tid;
    float accP[16], accQ[16];
#pragma unroll
    for (int r = 0; r < 16; r++) { accP[r] = 0.f; accQ[r] = 0.f; }
#pragma unroll 2
    for (int d = 0; d < 64; d++) {
        float wa = W1[d * 256 + c];
        float wb = W1[(64 + d) * 256 + c];
#pragma unroll
        for (int r = 0; r < 16; r++) {
            float e = es[r][d];
            accP[r] = fmaf(e, wa, accP[r]);
            accQ[r] = fmaf(e, wb, accQ[r]);
        }
    }
    float bb = b1[c];
#pragma unroll
    for (int r = 0; r < 16; r++) {
        g_P[(row0 + r) * 256 + c] = accP[r] + bb;
        g_Q[(row0 + r) * 256 + c] = accQ[r];
    }
}

// ---------------------------------------------------------------------------
// Kernel 2: persistent main. 148 blocks x 256 threads, 1 block/SM.
// Per tile (64 pairs x one k):
//   phase1: H[kk][m] = relu(P+Q) -> smem (stride 68)
//   phase2: register-blocked GEMM: warp tile 32m x 16d, thread 4m x 4d,
//           packed f32x2 FMAs, ~4 L1tex wavefronts per warp-kk for 512 FMA
//   epilogue: bias + embedding writes + Es stash; phase3: branch norms.
// ---------------------------------------------------------------------------
extern __shared__ float sm[];

__device__ __forceinline__ void ffma2(unsigned long long& acc,
                                      unsigned long long h,
                                      unsigned long long w) {
    asm("fma.rn.f32x2 %0, %1, %2, %0;" : "+l"(acc) : "l"(h), "l"(w));
}
__device__ __forceinline__ unsigned long long dup2(float x) {
    unsigned long long r;
    asm("mov.b64 %0, {%1, %2};" : "=l"(r) : "f"(x), "f"(x));
    return r;
}

__global__ void __launch_bounds__(256, 1) main_kernel(const float* __restrict__ embg,
                                                      const float* __restrict__ W2,
                                                      const float* __restrict__ b2g,
                                                      float* __restrict__ out) {
    float* W2s = sm;                 // 16384 floats (64 KB), layout [kk][d]
    float* Hs  = sm + 16384;         // 256*68 floats (69.6 KB), layout [kk][m]
    __shared__ int i1s[TJ], i2s[TJ];

    int tid = threadIdx.x;

    // Load W2 once per block
    {
        const float4* W2v = (const float4*)W2;
        float4* W2sv = (float4*)W2s;
#pragma unroll
        for (int q = 0; q < 16; q++) W2sv[tid + q * 256] = W2v[tid + q * 256];
    }

    int lane = tid & 31, w = tid >> 5;
    int mhalf = w & 1, wq = w >> 1;       // warp -> m half (32), d quarter (16)
    int dg = lane & 3, mgrp = lane >> 2;  // lane -> d group (4), m group (4)
    int m0 = mhalf * 32 + mgrp * 4;
    int d0 = wq * 16 + dg * 4;
    float4 bb4 = *(const float4*)&b2g[d0];
    float* out_emb = out + 4ull * KJ;

    for (int item = blockIdx.x; item < NTILES; item += GRID_MAIN) {
        int k    = item >> 5;             // item / 32
        int tile = item & 31;
        int jbase0 = tile * TJ;
        int nv = Jdim - jbase0; if (nv > TJ) nv = TJ;   // valid pairs this tile
        size_t jb = (size_t)k * Jdim + jbase0;

        __syncthreads();                  // prev tile's i1s/Es consumers done
        if (tid < TJ) {
            int j = jbase0 + tid;
            int jc = j < Jdim ? j : Jdim - 1;
            int2 p = g_pairs[jc];
            i1s[tid] = p.x; i2s[tid] = p.y;
            if (tid < nv) {
                out[jb + tid]              = (float)p.x;
                out[KJ + jb + tid]         = (float)p.y;
                out[68ull * KJ + jb + tid] = 0.f;
            }
        }
        __syncthreads();

        // -------- Phase 1: build H tile (thread = kk channel c) --------
        {
            int c = tid;
            const float* Pk = g_P + (size_t)k * Tdim * 256 + c;
            const float* Qk = g_Q + (size_t)k * Tdim * 256 + c;
            float* hrow = Hs + c * HS_STRIDE;
#pragma unroll
            for (int q = 0; q < 16; q++) {
                float4 v;
                float* vv = (float*)&v;
#pragma unroll
                for (int s = 0; s < 4; s++) {
                    int m = q * 4 + s;
                    float h = Pk[i1s[m] * 256] + Qk[i2s[m] * 256];
                    vv[s] = fmaxf(h, 0.f);
                }
                *(float4*)&hrow[q * 4] = v;
            }
        }
        __syncthreads();

        // -------- Phase 2: register-blocked GEMM over kk=256 --------
        unsigned long long acc[4][2];
#pragma unroll
        for (int mi = 0; mi < 4; mi++) { acc[mi][0] = 0; acc[mi][1] = 0; }
#pragma unroll 4
        for (int kk = 0; kk < 256; kk++) {
            float4 h4 = *(const float4*)&Hs[kk * HS_STRIDE + m0];
            ulonglong2 w2v = *(const ulonglong2*)&W2s[kk * 64 + d0];
            unsigned long long hd0 = dup2(h4.x);
            unsigned long long hd1 = dup2(h4.y);
            unsigned long long hd2 = dup2(h4.z);
            unsigned long long hd3 = dup2(h4.w);
            ffma2(acc[0][0], hd0, w2v.x); ffma2(acc[0][1], hd0, w2v.y);
            ffma2(acc[1][0], hd1, w2v.x); ffma2(acc[1][1], hd1, w2v.y);
            ffma2(acc[2][0], hd2, w2v.x); ffma2(acc[2][1], hd2, w2v.y);
            ffma2(acc[3][0], hd3, w2v.x); ffma2(acc[3][1], hd3, w2v.y);
        }
        __syncthreads();                  // Hs reads done -> reuse as Es

        // -------- Epilogue: bias, embedding writes, Es stash --------
        float* Es = Hs;                   // 64*64 floats
#pragma unroll
        for (int mi = 0; mi < 4; mi++) {
            float2 a0, a1;
            asm("mov.b64 {%0,%1}, %2;" : "=f"(a0.x), "=f"(a0.y) : "l"(acc[mi][0]));
            asm("mov.b64 {%0,%1}, %2;" : "=f"(a1.x), "=f"(a1.y) : "l"(acc[mi][1]));
            float4 e;
            e.x = a0.x + bb4.x; e.y = a0.y + bb4.y;
            e.z = a1.x + bb4.z; e.w = a1.y + bb4.w;
            int m = m0 + mi;
            if (m < nv) *(float4*)&out_emb[(jb + m) * 64 + d0] = e;
            *(float4*)&Es[m * 64 + d0] = e;
        }
        __syncthreads();

        // -------- Phase 3: branch norms (warp w -> pairs w*8..w*8+7) --------
        const float* embk = embg + (size_t)k * Tdim * Ddim;
#pragma unroll
        for (int q = 0; q < 8; q++) {
            int m  = w * 8 + q;
            int a1i = i1s[m], a2i = i2s[m];
            float e0 = Es[m * 64 + lane];
            float e1 = Es[m * 64 + lane + 32];
            float x0 = embk[a1i * 64 + lane]      - e0;
            float x1 = embk[a1i * 64 + lane + 32] - e1;
            float y0 = embk[a2i * 64 + lane]      - e0;
            float y1 = embk[a2i * 64 + lane + 32] - e1;
            float s1 = x0 * x0 + x1 * x1;
            float s2 = y0 * y0 + y1 * y1;
#pragma unroll
            for (int off = 16; off; off >>= 1) {
                s1 += __shfl_xor_sync(0xffffffff, s1, off);
                s2 += __shfl_xor_sync(0xffffffff, s2, off);
            }
            if (lane == 0 && m < nv) {
                out[2ull * KJ + jb + m] = sqrtf(s1);
                out[3ull * KJ + jb + m] = sqrtf(s2);
            }
        }
    }
}

// ---------------------------------------------------------------------------
extern "C" void kernel_launch(void* const* d_in, const int* in_sizes, int n_in,
                              void* d_out, int out_size) {
    const float *emb = 0, *W1 = 0, *b1 = 0, *W2 = 0, *b2 = 0;
    for (int i = 0; i < n_in; i++) {
        int s = in_sizes[i];
        if      (s == Kdim * Tdim * Ddim) emb = (const float*)d_in[i];
        else if (s == 2 * Ddim * Hdim)    W1  = (const float*)d_in[i];
        else if (s == Hdim)               b1  = (const float*)d_in[i];
        else if (s == Ddim)               b2  = (const float*)d_in[i];
        else if (s == Hdim * Ddim)        W2  = (const float*)d_in[i];  // last wins (hashes also 16384)
    }
    float* out = (float*)d_out;

    pq_kernel<<<(Kdim * Tdim) / 16, 256>>>(emb, W1, b1);

    const int smem_bytes = (16384 + 256 * HS_STRIDE) * sizeof(float);  // 135168
    cudaFuncSetAttribute(main_kernel, cudaFuncAttributeMaxDynamicSharedMemorySize, smem_bytes);
    main_kernel<<<GRID_MAIN, 256, smem_bytes>>>(emb, W2, b2, out);
}

// round 5
// speedup vs baseline: 1.3597x; 1.3597x over previous
#include <cuda_runtime.h>
#include <math.h>
#include <stdint.h>

#define Kdim 256
#define Tdim 64
#define Ddim 64
#define Hdim 256
#define Jdim 2016                  // 64*63/2
#define KJ   (Kdim*Jdim)           // 516096
#define TJ   128                   // pairs per tile
#define TILES_PER_K 16             // ceil(2016/128) — last tile ragged (96 valid)
#define NTILES (Kdim*TILES_PER_K)  // 4096
#define HS_STRIDE 132              // padded word stride for H tile rows (128 m + 4 pad)
#define GRID_MAIN 148              // 1 persistent block per SM
#define NTHR 512

// Scratch (device globals — no allocation allowed)
__device__ float g_P[Kdim*Tdim*Hdim];   // 16.8 MB: emb @ W1[:64] + b1
__device__ float g_Q[Kdim*Tdim*Hdim];   // 16.8 MB: emb @ W1[64:]
__device__ int2  g_pairs[Jdim];

// ---------------------------------------------------------------------------
// Kernel 1: P/Q precompute (+ pair table from block 0). 256 thr, 16 rows/blk.
// ---------------------------------------------------------------------------
__global__ void __launch_bounds__(256) pq_kernel(const float* __restrict__ emb,
                                                 const float* __restrict__ W1,
                                                 const float* __restrict__ b1) {
    if (blockIdx.x == 0 && threadIdx.x < Tdim - 1) {
        int i = threadIdx.x;
        int start = i * (Tdim - 1) - i * (i - 1) / 2;
        for (int j = i + 1; j < Tdim; j++) g_pairs[start++] = make_int2(i, j);
    }
    __shared__ float es[16][64];
    int row0 = blockIdx.x * 16;
    int tid = threadIdx.x;
#pragma unroll
    for (int q = 0; q < 4; q++) {
        int v = tid + q * 256;
        es[v >> 6][v & 63] = emb[row0 * 64 + v];
    }
    __syncthreads();
    int c = tid;
    float accP[16], accQ[16];
#pragma unroll
    for (int r = 0; r < 16; r++) { accP[r] = 0.f; accQ[r] = 0.f; }
#pragma unroll 2
    for (int d = 0; d < 64; d++) {
        float wa = W1[d * 256 + c];
        float wb = W1[(64 + d) * 256 + c];
#pragma unroll
        for (int r = 0; r < 16; r++) {
            float e = es[r][d];
            accP[r] = fmaf(e, wa, accP[r]);
            accQ[r] = fmaf(e, wb, accQ[r]);
        }
    }
    float bb = b1[c];
#pragma unroll
    for (int r = 0; r < 16; r++) {
        g_P[(row0 + r) * 256 + c] = accP[r] + bb;
        g_Q[(row0 + r) * 256 + c] = accQ[r];
    }
}

// ---------------------------------------------------------------------------
// Kernel 2: persistent main. 148 blocks x 512 threads (16 warps), 1 block/SM.
// Per tile (128 pairs x one k):
//   phase1: H[kk][m] = relu(P+Q) -> smem (stride 132); 2 threads per kk row
//   phase2: register-blocked GEMM: warp tile 32m x 16d, thread 4m x 4d,
//           packed f32x2 FMAs (~128 FMA per L1tex wavefront)
//   epilogue: bias + embedding writes + Es stash; phase3: branch norms.
// ---------------------------------------------------------------------------
extern __shared__ float sm[];

__device__ __forceinline__ void ffma2(unsigned long long& acc,
                                      unsigned long long h,
                                      unsigned long long w) {
    asm("fma.rn.f32x2 %0, %1, %2, %0;" : "+l"(acc) : "l"(h), "l"(w));
}
__device__ __forceinline__ unsigned long long dup2(float x) {
    unsigned long long r;
    asm("mov.b64 %0, {%1, %2};" : "=l"(r) : "f"(x), "f"(x));
    return r;
}

__global__ void __launch_bounds__(NTHR, 1) main_kernel(const float* __restrict__ embg,
                                                       const float* __restrict__ W2,
                                                       const float* __restrict__ b2g,
                                                       float* __restrict__ out) {
    float* W2s = sm;                 // 16384 floats (64 KB), layout [kk][d]
    float* Hs  = sm + 16384;         // 256*132 floats (132 KB), layout [kk][m]
    __shared__ int i1s[TJ], i2s[TJ];

    int tid = threadIdx.x;

    // Load W2 once per block
    {
        const float4* W2v = (const float4*)W2;
        float4* W2sv = (float4*)W2s;
#pragma unroll
        for (int q = 0; q < 8; q++) W2sv[tid + q * NTHR] = W2v[tid + q * NTHR];
    }

    int lane = tid & 31, w = tid >> 5;
    // phase-2 mapping: 16 warps = 4 m-quads x 4 d-quads
    int mq = w & 3, wq = w >> 2;
    int m0 = mq * 32 + (lane >> 2) * 4;
    int d0 = wq * 16 + (lane & 3) * 4;
    // phase-1 mapping: 2 threads per kk row, 64 m each
    int c1 = tid & 255, half1 = tid >> 8;
    float4 bb4 = *(const float4*)&b2g[d0];
    float* out_emb = out + 4ull * KJ;

    for (int item = blockIdx.x; item < NTILES; item += GRID_MAIN) {
        int k    = item >> 4;             // item / 16
        int tile = item & 15;
        int jbase0 = tile * TJ;
        int nv = Jdim - jbase0; if (nv > TJ) nv = TJ;   // valid pairs this tile
        size_t jb = (size_t)k * Jdim + jbase0;

        __syncthreads();                  // prev tile's consumers done
        if (tid < TJ) {
            int j = jbase0 + tid;
            int jc = j < Jdim ? j : Jdim - 1;
            int2 p = g_pairs[jc];
            i1s[tid] = p.x; i2s[tid] = p.y;
            if (tid < nv) {
                out[jb + tid]              = (float)p.x;
                out[KJ + jb + tid]         = (float)p.y;
                out[68ull * KJ + jb + tid] = 0.f;
            }
        }
        __syncthreads();

        // -------- Phase 1: build H tile --------
        {
            const float* Pk = g_P + (size_t)k * Tdim * 256 + c1;
            const float* Qk = g_Q + (size_t)k * Tdim * 256 + c1;
            float* hrow = Hs + c1 * HS_STRIDE + half1 * 64;
#pragma unroll
            for (int q = 0; q < 16; q++) {
                float4 v;
                float* vv = (float*)&v;
#pragma unroll
                for (int s = 0; s < 4; s++) {
                    int m = half1 * 64 + q * 4 + s;
                    float h = Pk[i1s[m] * 256] + Qk[i2s[m] * 256];
                    vv[s] = fmaxf(h, 0.f);
                }
                *(float4*)&hrow[q * 4] = v;
            }
        }
        __syncthreads();

        // -------- Phase 2: register-blocked GEMM over kk=256 --------
        unsigned long long acc[4][2];
#pragma unroll
        for (int mi = 0; mi < 4; mi++) { acc[mi][0] = 0; acc[mi][1] = 0; }
#pragma unroll 4
        for (int kk = 0; kk < 256; kk++) {
            float4 h4 = *(const float4*)&Hs[kk * HS_STRIDE + m0];
            ulonglong2 w2v = *(const ulonglong2*)&W2s[kk * 64 + d0];
            unsigned long long hd0 = dup2(h4.x);
            unsigned long long hd1 = dup2(h4.y);
            unsigned long long hd2 = dup2(h4.z);
            unsigned long long hd3 = dup2(h4.w);
            ffma2(acc[0][0], hd0, w2v.x); ffma2(acc[0][1], hd0, w2v.y);
            ffma2(acc[1][0], hd1, w2v.x); ffma2(acc[1][1], hd1, w2v.y);
            ffma2(acc[2][0], hd2, w2v.x); ffma2(acc[2][1], hd2, w2v.y);
            ffma2(acc[3][0], hd3, w2v.x); ffma2(acc[3][1], hd3, w2v.y);
        }
        __syncthreads();                  // Hs reads done -> reuse as Es

        // -------- Epilogue: bias, embedding writes, Es stash --------
        float* Es = Hs;                   // 128*64 floats
#pragma unroll
        for (int mi = 0; mi < 4; mi++) {
            float2 a0, a1;
            asm("mov.b64 {%0,%1}, %2;" : "=f"(a0.x), "=f"(a0.y) : "l"(acc[mi][0]));
            asm("mov.b64 {%0,%1}, %2;" : "=f"(a1.x), "=f"(a1.y) : "l"(acc[mi][1]));
            float4 e;
            e.x = a0.x + bb4.x; e.y = a0.y + bb4.y;
            e.z = a1.x + bb4.z; e.w = a1.y + bb4.w;
            int m = m0 + mi;
            if (m < nv) *(float4*)&out_emb[(jb + m) * 64 + d0] = e;
            *(float4*)&Es[m * 64 + d0] = e;
        }
        __syncthreads();

        // -------- Phase 3: branch norms (warp w -> pairs w*8..w*8+7) --------
        const float* embk = embg + (size_t)k * Tdim * Ddim;
#pragma unroll
        for (int q = 0; q < 8; q++) {
            int m  = w * 8 + q;
            int a1i = i1s[m], a2i = i2s[m];
            float e0 = Es[m * 64 + lane];
            float e1 = Es[m * 64 + lane + 32];
            float x0 = embk[a1i * 64 + lane]      - e0;
            float x1 = embk[a1i * 64 + lane + 32] - e1;
            float y0 = embk[a2i * 64 + lane]      - e0;
            float y1 = embk[a2i * 64 + lane + 32] - e1;
            float s1 = x0 * x0 + x1 * x1;
            float s2 = y0 * y0 + y1 * y1;
#pragma unroll
            for (int off = 16; off; off >>= 1) {
                s1 += __shfl_xor_sync(0xffffffff, s1, off);
                s2 += __shfl_xor_sync(0xffffffff, s2, off);
            }
            if (lane == 0 && m < nv) {
                out[2ull * KJ + jb + m] = sqrtf(s1);
                out[3ull * KJ + jb + m] = sqrtf(s2);
            }
        }
    }
}

// ---------------------------------------------------------------------------
extern "C" void kernel_launch(void* const* d_in, const int* in_sizes, int n_in,
                              void* d_out, int out_size) {
    const float *emb = 0, *W1 = 0, *b1 = 0, *W2 = 0, *b2 = 0;
    for (int i = 0; i < n_in; i++) {
        int s = in_sizes[i];
        if      (s == Kdim * Tdim * Ddim) emb = (const float*)d_in[i];
        else if (s == 2 * Ddim * Hdim)    W1  = (const float*)d_in[i];
        else if (s == Hdim)               b1  = (const float*)d_in[i];
        else if (s == Ddim)               b2  = (const float*)d_in[i];
        else if (s == Hdim * Ddim)        W2  = (const float*)d_in[i];  // last wins (hashes also 16384)
    }
    float* out = (float*)d_out;

    pq_kernel<<<(Kdim * Tdim) / 16, 256>>>(emb, W1, b1);

    const int smem_bytes = (16384 + 256 * HS_STRIDE) * sizeof(float);  // 200704
    cudaFuncSetAttribute(main_kernel, cudaFuncAttributeMaxDynamicSharedMemorySize, smem_bytes);
    main_kernel<<<GRID_MAIN, NTHR, smem_bytes>>>(emb, W2, b2, out);
}

// round 14
// speedup vs baseline: 2.0426x; 1.5022x over previous
#include <cuda_runtime.h>
#include <cuda_bf16.h>
#include <math.h>
#include <stdint.h>

#define Kdim 256
#define Tdim 64
#define Ddim 64
#define Hdim 256
#define Jdim 2016                  // 64*63/2
#define KJ   (Kdim*Jdim)           // 516096
#define TJ   128                   // pairs per tile
#define TILES_PER_K 16             // last tile ragged (96 valid)
#define NTILES (Kdim*TILES_PER_K)  // 4096
#define GRID_MAIN 148
#define NTHR 512
#define ES_S 68                    // word stride over m rows of Es [128 m][64 d]

// bf16 tile strides (bytes): 264 bf16 = 528 B; 528 mod 128 = 16 -> ldmatrix
// row addresses cycle through all 16B banks, conflict-free.
#define A_STRIDE 528
#define B_STRIDE 528

// Dynamic smem layout (bytes). Es ([128][68] floats = 34816 B) aliases Ahi.
#define OFF_AHI 0
#define OFF_ALO (128 * A_STRIDE)                 // 67584
#define OFF_BHI (2 * 128 * A_STRIDE)             // 135168
#define OFF_BLO (OFF_BHI + 64 * B_STRIDE)        // 168960
#define SMEM_BYTES (OFF_BLO + 64 * B_STRIDE)     // 202752

// Scratch (device globals — no allocation allowed)
__device__ float g_P[Kdim*Tdim*Hdim];   // emb @ W1[:64] + b1
__device__ float g_Q[Kdim*Tdim*Hdim];   // emb @ W1[64:]
__device__ int2  g_pairs[Jdim];

__device__ __forceinline__ uint32_t smem_u32(const void* p) {
    uint32_t a;
    asm("{ .reg .u64 t; cvta.to.shared.u64 t, %1; cvt.u32.u64 %0, t; }" : "=r"(a) : "l"(p));
    return a;
}
__device__ __forceinline__ void ldsm_x4(uint32_t* r, uint32_t addr) {
    asm volatile("ldmatrix.sync.aligned.m8n8.x4.shared.b16 {%0,%1,%2,%3}, [%4];"
                 : "=r"(r[0]), "=r"(r[1]), "=r"(r[2]), "=r"(r[3]) : "r"(addr));
}
__device__ __forceinline__ void mma_bf16(float* c, const uint32_t* a, uint32_t b0, uint32_t b1) {
    asm volatile(
        "mma.sync.aligned.m16n8k16.row.col.f32.bf16.bf16.f32 "
        "{%0,%1,%2,%3}, {%4,%5,%6,%7}, {%8,%9}, {%0,%1,%2,%3};"
        : "+f"(c[0]), "+f"(c[1]), "+f"(c[2]), "+f"(c[3])
        : "r"(a[0]), "r"(a[1]), "r"(a[2]), "r"(a[3]), "r"(b0), "r"(b1));
}

// ---------------------------------------------------------------------------
// Kernel 1: P/Q precompute (+ pair table from block 0). 256 thr, 16 rows/blk.
// ---------------------------------------------------------------------------
__global__ void __launch_bounds__(256) pq_kernel(const float* __restrict__ emb,
                                                 const float* __restrict__ W1,
                                                 const float* __restrict__ b1) {
    if (blockIdx.x == 0 && threadIdx.x < Tdim - 1) {
        int i = threadIdx.x;
        int start = i * (Tdim - 1) - i * (i - 1) / 2;
        for (int j = i + 1; j < Tdim; j++) g_pairs[start++] = make_int2(i, j);
    }
    __shared__ float es[16][64];
    int row0 = blockIdx.x * 16;
    int tid = threadIdx.x;
#pragma unroll
    for (int q = 0; q < 4; q++) {
        int v = tid + q * 256;
        es[v >> 6][v & 63] = emb[row0 * 64 + v];
    }
    __syncthreads();
    int c = tid;
    float accP[16], accQ[16];
#pragma unroll
    for (int r = 0; r < 16; r++) { accP[r] = 0.f; accQ[r] = 0.f; }
#pragma unroll 2
    for (int d = 0; d < 64; d++) {
        float wa = W1[d * 256 + c];
        float wb = W1[(64 + d) * 256 + c];
#pragma unroll
        for (int r = 0; r < 16; r++) {
            float e = es[r][d];
            accP[r] = fmaf(e, wa, accP[r]);
            accQ[r] = fmaf(e, wb, accQ[r]);
        }
    }
    float bb = b1[c];
#pragma unroll
    for (int r = 0; r < 16; r++) {
        g_P[(row0 + r) * 256 + c] = accP[r] + bb;
        g_Q[(row0 + r) * 256 + c] = accQ[r];
    }
}

// ---------------------------------------------------------------------------
// Kernel 2: persistent main. mma.sync bf16x3 GEMM2 (legacy HMMA, sm_100-safe).
// Per tile (128 pairs x one k):
//   phase1: H = relu(P+Q), bf16 hi/lo split -> Ahi/Alo [128 m][264 kk]
//   GEMM:   warp tile m16 x d32, 16 k-steps, 3 passes (hh, hl, lh)
//   epilogue: bias + emb writes + Es[m][d] (aliases Ahi); phase3: norms.
// ---------------------------------------------------------------------------
__global__ void __launch_bounds__(NTHR, 1)
main_kernel(const float* __restrict__ embg,
            const float* __restrict__ W2,
            const float* __restrict__ b2g,
            float* __restrict__ out) {
    extern __shared__ char dsm[];
    __shared__ int i1s[TJ], i2s[TJ];
    __shared__ float b2s[64];

    char* pAhi = dsm + OFF_AHI;
    char* pAlo = dsm + OFF_ALO;
    char* pBhi = dsm + OFF_BHI;
    char* pBlo = dsm + OFF_BLO;
    float* Es  = (float*)(dsm + OFF_AHI);      // [128][ES_S] floats, aliases Ahi
    uint32_t smBase = smem_u32(dsm);
    uint32_t smAhi = smBase + OFF_AHI, smAlo = smBase + OFF_ALO;
    uint32_t smBhi = smBase + OFF_BHI, smBlo = smBase + OFF_BLO;

    int tid = threadIdx.x;
    int lane = tid & 31, w = tid >> 5;
    if (tid < 64) b2s[tid] = b2g[tid];

    // ---- Build B = W2^T hi/lo bf16 [64 d][264 kk] once per block ----
    {
        float* W2f = (float*)pAhi;             // stage fp32 W2 (A region, pre-use)
        const float4* W2v = (const float4*)W2;
#pragma unroll
        for (int q = 0; q < 8; q++) ((float4*)W2f)[tid + q * NTHR] = W2v[tid + q * NTHR];
        __syncthreads();
        int d = tid >> 3, kk0 = (tid & 7) * 32;
        for (int i = 0; i < 32; i++) {
            int kk = kk0 + i;
            float v = W2f[kk * 64 + d];
            __nv_bfloat16 bh = __float2bfloat16_rn(v);
            __nv_bfloat16 bl = __float2bfloat16_rn(v - __bfloat162float(bh));
            *(unsigned short*)(pBhi + d * B_STRIDE + kk * 2) = __bfloat16_as_ushort(bh);
            *(unsigned short*)(pBlo + d * B_STRIDE + kk * 2) = __bfloat16_as_ushort(bl);
        }
        __syncthreads();
    }

    float* out_emb = out + 4ull * KJ;
    // phase-1 mapping: warp w covers m = mb*8 + (w>>1); lanes give 4-kk groups
    int m1base = w >> 1;
    int kkl = ((w & 1) * 32 + lane) * 4;       // 0..252 step 4
    // GEMM mapping: warp w -> m-block (w&7)*16, d-block (w>>3)*32
    int m0w = (w & 7) * 16, d0w = (w >> 3) * 32;
    // ldmatrix lane addressing (bytes)
    uint32_t aRowOff = (uint32_t)(m0w + (lane & 15)) * A_STRIDE + ((lane >> 4) * 16);
    uint32_t bRowOff0 = (uint32_t)(d0w + ((lane >> 4) << 3) + (lane & 7)) * B_STRIDE + (((lane >> 3) & 1) * 16);
    uint32_t bRowOff1 = bRowOff0 + 16u * B_STRIDE;

    for (int item = blockIdx.x; item < NTILES; item += GRID_MAIN) {
        int k    = item >> 4;
        int tile = item & 15;
        int jbase0 = tile * TJ;
        int nv = Jdim - jbase0; if (nv > TJ) nv = TJ;
        size_t jb = (size_t)k * Jdim + jbase0;

        __syncthreads();                       // prev tile fully consumed
        if (tid < TJ) {
            int j = jbase0 + tid;
            int jc = j < Jdim ? j : Jdim - 1;
            int2 p = g_pairs[jc];
            i1s[tid] = p.x; i2s[tid] = p.y;
            if (tid < nv) {
                out[jb + tid]              = (float)p.x;
                out[KJ + jb + tid]         = (float)p.y;
                out[68ull * KJ + jb + tid] = 0.f;
            }
        }
        __syncthreads();

        // -------- Phase 1: H = relu(P+Q) -> bf16 hi/lo A tiles --------
        {
            const float* __restrict__ Pk = g_P + (size_t)k * Tdim * 256;
            const float* __restrict__ Qk = g_Q + (size_t)k * Tdim * 256;
#pragma unroll 2
            for (int mb = 0; mb < 16; mb++) {
                int m = mb * 8 + m1base;
                float4 p = *(const float4*)&Pk[i1s[m] * 256 + kkl];
                float4 q = *(const float4*)&Qk[i2s[m] * 256 + kkl];
                float h0 = fmaxf(p.x + q.x, 0.f), h1 = fmaxf(p.y + q.y, 0.f);
                float h2 = fmaxf(p.z + q.z, 0.f), h3 = fmaxf(p.w + q.w, 0.f);
                __nv_bfloat16 a0 = __float2bfloat16_rn(h0), a1 = __float2bfloat16_rn(h1);
                __nv_bfloat16 a2 = __float2bfloat16_rn(h2), a3 = __float2bfloat16_rn(h3);
                __nv_bfloat16 l0 = __float2bfloat16_rn(h0 - __bfloat162float(a0));
                __nv_bfloat16 l1 = __float2bfloat16_rn(h1 - __bfloat162float(a1));
                __nv_bfloat16 l2 = __float2bfloat16_rn(h2 - __bfloat162float(a2));
                __nv_bfloat16 l3 = __float2bfloat16_rn(h3 - __bfloat162float(a3));
                uint2 hv, lv;
                hv.x = (uint32_t)__bfloat16_as_ushort(a1) << 16 | __bfloat16_as_ushort(a0);
                hv.y = (uint32_t)__bfloat16_as_ushort(a3) << 16 | __bfloat16_as_ushort(a2);
                lv.x = (uint32_t)__bfloat16_as_ushort(l1) << 16 | __bfloat16_as_ushort(l0);
                lv.y = (uint32_t)__bfloat16_as_ushort(l3) << 16 | __bfloat16_as_ushort(l2);
                uint32_t off = (uint32_t)m * A_STRIDE + kkl * 2;
                *(uint2*)(pAhi + off) = hv;
                *(uint2*)(pAlo + off) = lv;
            }
        }
        __syncthreads();

        // -------- GEMM: warp m16 x d32, 16 k-steps, bf16x3 --------
        float acc[4][4];
#pragma unroll
        for (int t = 0; t < 4; t++)
#pragma unroll
            for (int i = 0; i < 4; i++) acc[t][i] = 0.f;
#pragma unroll 4
        for (int ks = 0; ks < 16; ks++) {
            uint32_t koff = (uint32_t)ks * 32;
            uint32_t ah[4], al[4], bh[8], bl[8];
            ldsm_x4(ah, smAhi + aRowOff + koff);
            ldsm_x4(al, smAlo + aRowOff + koff);
            ldsm_x4(bh,     smBhi + bRowOff0 + koff);
            ldsm_x4(bh + 4, smBhi + bRowOff1 + koff);
            ldsm_x4(bl,     smBlo + bRowOff0 + koff);
            ldsm_x4(bl + 4, smBlo + bRowOff1 + koff);
#pragma unroll
            for (int t = 0; t < 4; t++) {
                mma_bf16(acc[t], ah, bh[t * 2], bh[t * 2 + 1]);   // hi*hi
                mma_bf16(acc[t], ah, bl[t * 2], bl[t * 2 + 1]);   // hi*lo
                mma_bf16(acc[t], al, bh[t * 2], bh[t * 2 + 1]);   // lo*hi
            }
        }
        __syncthreads();                       // A tiles fully read -> Es may alias Ahi

        // -------- Epilogue: bias, emb writes, Es[m][d] stash --------
        {
            int mlo = m0w + (lane >> 2);
            int mhi = mlo + 8;
            bool vlo = mlo < nv, vhi = mhi < nv;
#pragma unroll
            for (int t = 0; t < 4; t++) {
                int d = d0w + t * 8 + (lane & 3) * 2;
                float bx = b2s[d], by = b2s[d + 1];
                float e0 = acc[t][0] + bx, e1 = acc[t][1] + by;
                float e2 = acc[t][2] + bx, e3 = acc[t][3] + by;
                if (vlo) *(float2*)&out_emb[(jb + mlo) * 64 + d] = make_float2(e0, e1);
                if (vhi) *(float2*)&out_emb[(jb + mhi) * 64 + d] = make_float2(e2, e3);
                *(float2*)&Es[mlo * ES_S + d] = make_float2(e0, e1);
                *(float2*)&Es[mhi * ES_S + d] = make_float2(e2, e3);
            }
        }
        __syncthreads();

        // -------- Phase 3: branch norms (warp w -> pairs w*8..w*8+7) --------
        const float* embk = embg + (size_t)k * Tdim * Ddim;
#pragma unroll
        for (int q = 0; q < 8; q++) {
            int m  = w * 8 + q;
            int a1i = i1s[m], a2i = i2s[m];
            float e0 = Es[m * ES_S + lane];
            float e1 = Es[m * ES_S + lane + 32];
            float x0 = embk[a1i * 64 + lane]      - e0;
            float x1 = embk[a1i * 64 + lane + 32] - e1;
            float y0 = embk[a2i * 64 + lane]      - e0;
            float y1 = embk[a2i * 64 + lane + 32] - e1;
            float s1 = x0 * x0 + x1 * x1;
            float s2 = y0 * y0 + y1 * y1;
#pragma unroll
            for (int off = 16; off; off >>= 1) {
                s1 += __shfl_xor_sync(0xffffffff, s1, off);
                s2 += __shfl_xor_sync(0xffffffff, s2, off);
            }
            if (lane == 0 && m < nv) {
                out[2ull * KJ + jb + m] = sqrtf(s1);
                out[3ull * KJ + jb + m] = sqrtf(s2);
            }
        }
    }
}

// ---------------------------------------------------------------------------
extern "C" void kernel_launch(void* const* d_in, const int* in_sizes, int n_in,
                              void* d_out, int out_size) {
    const float *emb = 0, *W1 = 0, *b1 = 0, *W2 = 0, *b2 = 0;
    for (int i = 0; i < n_in; i++) {
        int s = in_sizes[i];
        if      (s == Kdim * Tdim * Ddim) emb = (const float*)d_in[i];
        else if (s == 2 * Ddim * Hdim)    W1  = (const float*)d_in[i];
        else if (s == Hdim)               b1  = (const float*)d_in[i];
        else if (s == Ddim)               b2  = (const float*)d_in[i];
        else if (s == Hdim * Ddim)        W2  = (const float*)d_in[i];  // last wins (hashes also 16384)
    }
    float* out = (float*)d_out;

    pq_kernel<<<(Kdim * Tdim) / 16, 256>>>(emb, W1, b1);

    cudaFuncSetAttribute(main_kernel, cudaFuncAttributeMaxDynamicSharedMemorySize, SMEM_BYTES);
    main_kernel<<<GRID_MAIN, NTHR, SMEM_BYTES>>>(emb, W2, b2, out);
}

// round 15
// speedup vs baseline: 2.0512x; 1.0042x over previous
#include <cuda_runtime.h>
#include <cuda_bf16.h>
#include <math.h>
#include <stdint.h>

#define Kdim 256
#define Tdim 64
#define Ddim 64
#define Hdim 256
#define Jdim 2016                  // 64*63/2
#define KJ   (Kdim*Jdim)           // 516096
#define TJ   128                   // pairs per tile
#define TILES_PER_K 16             // last tile ragged (96 valid)
#define NTILES (Kdim*TILES_PER_K)  // 4096
#define GRID_MAIN 148
#define NTHR 512
#define ES_S 68                    // word stride over m rows of Es [128 m][64 d]

// bf16 tile strides (bytes): 264 bf16 = 528 B; 528 mod 128 = 16 -> ldmatrix
// row addresses cycle through all 16B banks, conflict-free.
#define A_STRIDE 528
#define B_STRIDE 528

// Dynamic smem layout (bytes). Es ([128][68] floats = 34816 B) aliases Ahi.
#define OFF_AHI 0
#define OFF_ALO (128 * A_STRIDE)                 // 67584
#define OFF_BHI (2 * 128 * A_STRIDE)             // 135168
#define OFF_BLO (OFF_BHI + 64 * B_STRIDE)        // 168960
#define SMEM_BYTES (OFF_BLO + 64 * B_STRIDE)     // 202752

// Scratch (device globals — no allocation allowed)
__device__ float g_P[Kdim*Tdim*Hdim];   // emb @ W1[:64] + b1
__device__ float g_Q[Kdim*Tdim*Hdim];   // emb @ W1[64:]
__device__ int2  g_pairs[Jdim];

__device__ __forceinline__ uint32_t smem_u32(const void* p) {
    uint32_t a;
    asm("{ .reg .u64 t; cvta.to.shared.u64 t, %1; cvt.u32.u64 %0, t; }" : "=r"(a) : "l"(p));
    return a;
}
__device__ __forceinline__ void ldsm_x4(uint32_t* r, uint32_t addr) {
    asm volatile("ldmatrix.sync.aligned.m8n8.x4.shared.b16 {%0,%1,%2,%3}, [%4];"
                 : "=r"(r[0]), "=r"(r[1]), "=r"(r[2]), "=r"(r[3]) : "r"(addr));
}
__device__ __forceinline__ void mma_bf16(float* c, const uint32_t* a, uint32_t b0, uint32_t b1) {
    asm volatile(
        "mma.sync.aligned.m16n8k16.row.col.f32.bf16.bf16.f32 "
        "{%0,%1,%2,%3}, {%4,%5,%6,%7}, {%8,%9}, {%0,%1,%2,%3};"
        : "+f"(c[0]), "+f"(c[1]), "+f"(c[2]), "+f"(c[3])
        : "r"(a[0]), "r"(a[1]), "r"(a[2]), "r"(a[3]), "r"(b0), "r"(b1));
}

// ---------------------------------------------------------------------------
// Kernel 1: P/Q precompute (+ pair table from block 0). 256 thr, 16 rows/blk.
// ---------------------------------------------------------------------------
__global__ void __launch_bounds__(256) pq_kernel(const float* __restrict__ emb,
                                                 const float* __restrict__ W1,
                                                 const float* __restrict__ b1) {
    if (blockIdx.x == 0 && threadIdx.x < Tdim - 1) {
        int i = threadIdx.x;
        int start = i * (Tdim - 1) - i * (i - 1) / 2;
        for (int j = i + 1; j < Tdim; j++) g_pairs[start++] = make_int2(i, j);
    }
    __shared__ float es[16][64];
    int row0 = blockIdx.x * 16;
    int tid = threadIdx.x;
#pragma unroll
    for (int q = 0; q < 4; q++) {
        int v = tid + q * 256;
        es[v >> 6][v & 63] = emb[row0 * 64 + v];
    }
    __syncthreads();
    int c = tid;
    float accP[16], accQ[16];
#pragma unroll
    for (int r = 0; r < 16; r++) { accP[r] = 0.f; accQ[r] = 0.f; }
#pragma unroll 2
    for (int d = 0; d < 64; d++) {
        float wa = W1[d * 256 + c];
        float wb = W1[(64 + d) * 256 + c];
#pragma unroll
        for (int r = 0; r < 16; r++) {
            float e = es[r][d];
            accP[r] = fmaf(e, wa, accP[r]);
            accQ[r] = fmaf(e, wb, accQ[r]);
        }
    }
    float bb = b1[c];
#pragma unroll
    for (int r = 0; r < 16; r++) {
        g_P[(row0 + r) * 256 + c] = accP[r] + bb;
        g_Q[(row0 + r) * 256 + c] = accQ[r];
    }
}

// ---------------------------------------------------------------------------
// Kernel 2: persistent main. mma.sync bf16x3 GEMM2 (legacy HMMA, sm_100-safe).
// Per tile (128 pairs x one k):
//   phase1: H = relu(P+Q), bf16 hi/lo split -> Ahi/Alo [128 m][264 kk]
//   GEMM:   warp tile m16 x d32, 16 k-steps, 3 passes (hh, hl, lh)
//   epilogue: bias + emb writes + Es[m][d] (aliases Ahi); phase3: norms.
// ---------------------------------------------------------------------------
__global__ void __launch_bounds__(NTHR, 1)
main_kernel(const float* __restrict__ embg,
            const float* __restrict__ W2,
            const float* __restrict__ b2g,
            float* __restrict__ out) {
    extern __shared__ char dsm[];
    __shared__ int i1s[TJ], i2s[TJ];
    __shared__ float b2s[64];

    char* pAhi = dsm + OFF_AHI;
    char* pAlo = dsm + OFF_ALO;
    char* pBhi = dsm + OFF_BHI;
    char* pBlo = dsm + OFF_BLO;
    float* Es  = (float*)(dsm + OFF_AHI);      // [128][ES_S] floats, aliases Ahi
    uint32_t smBase = smem_u32(dsm);
    uint32_t smAhi = smBase + OFF_AHI, smAlo = smBase + OFF_ALO;
    uint32_t smBhi = smBase + OFF_BHI, smBlo = smBase + OFF_BLO;

    int tid = threadIdx.x;
    int lane = tid & 31, w = tid >> 5;
    if (tid < 64) b2s[tid] = b2g[tid];

    // ---- Build B = W2^T hi/lo bf16 [64 d][264 kk] once per block ----
    {
        float* W2f = (float*)pAhi;             // stage fp32 W2 (A region, pre-use)
        const float4* W2v = (const float4*)W2;
#pragma unroll
        for (int q = 0; q < 8; q++) ((float4*)W2f)[tid + q * NTHR] = W2v[tid + q * NTHR];
        __syncthreads();
        int d = tid >> 3, kk0 = (tid & 7) * 32;
        for (int i = 0; i < 32; i++) {
            int kk = kk0 + i;
            float v = W2f[kk * 64 + d];
            __nv_bfloat16 bh = __float2bfloat16_rn(v);
            __nv_bfloat16 bl = __float2bfloat16_rn(v - __bfloat162float(bh));
            *(unsigned short*)(pBhi + d * B_STRIDE + kk * 2) = __bfloat16_as_ushort(bh);
            *(unsigned short*)(pBlo + d * B_STRIDE + kk * 2) = __bfloat16_as_ushort(bl);
        }
        __syncthreads();
    }

    float* out_emb = out + 4ull * KJ;
    // phase-1 mapping: warp w covers m = mb*8 + (w>>1); lanes give 4-kk groups
    int m1base = w >> 1;
    int kkl = ((w & 1) * 32 + lane) * 4;       // 0..252 step 4
    // GEMM mapping: warp w -> m-block (w&7)*16, d-block (w>>3)*32
    int m0w = (w & 7) * 16, d0w = (w >> 3) * 32;
    // ldmatrix lane addressing (bytes)
    uint32_t aRowOff = (uint32_t)(m0w + (lane & 15)) * A_STRIDE + ((lane >> 4) * 16);
    uint32_t bRowOff0 = (uint32_t)(d0w + ((lane >> 4) << 3) + (lane & 7)) * B_STRIDE + (((lane >> 3) & 1) * 16);
    uint32_t bRowOff1 = bRowOff0 + 16u * B_STRIDE;

    for (int item = blockIdx.x; item < NTILES; item += GRID_MAIN) {
        int k    = item >> 4;
        int tile = item & 15;
        int jbase0 = tile * TJ;
        int nv = Jdim - jbase0; if (nv > TJ) nv = TJ;
        size_t jb = (size_t)k * Jdim + jbase0;

        __syncthreads();                       // prev tile fully consumed
        if (tid < TJ) {
            int j = jbase0 + tid;
            int jc = j < Jdim ? j : Jdim - 1;
            int2 p = g_pairs[jc];
            i1s[tid] = p.x; i2s[tid] = p.y;
            if (tid < nv) {
                out[jb + tid]              = (float)p.x;
                out[KJ + jb + tid]         = (float)p.y;
                out[68ull * KJ + jb + tid] = 0.f;
            }
        }
        __syncthreads();

        // -------- Phase 1: H = relu(P+Q) -> bf16 hi/lo A tiles --------
        {
            const float* __restrict__ Pk = g_P + (size_t)k * Tdim * 256;
            const float* __restrict__ Qk = g_Q + (size_t)k * Tdim * 256;
#pragma unroll 2
            for (int mb = 0; mb < 16; mb++) {
                int m = mb * 8 + m1base;
                float4 p = *(const float4*)&Pk[i1s[m] * 256 + kkl];
                float4 q = *(const float4*)&Qk[i2s[m] * 256 + kkl];
                float h0 = fmaxf(p.x + q.x, 0.f), h1 = fmaxf(p.y + q.y, 0.f);
                float h2 = fmaxf(p.z + q.z, 0.f), h3 = fmaxf(p.w + q.w, 0.f);
                __nv_bfloat16 a0 = __float2bfloat16_rn(h0), a1 = __float2bfloat16_rn(h1);
                __nv_bfloat16 a2 = __float2bfloat16_rn(h2), a3 = __float2bfloat16_rn(h3);
                __nv_bfloat16 l0 = __float2bfloat16_rn(h0 - __bfloat162float(a0));
                __nv_bfloat16 l1 = __float2bfloat16_rn(h1 - __bfloat162float(a1));
                __nv_bfloat16 l2 = __float2bfloat16_rn(h2 - __bfloat162float(a2));
                __nv_bfloat16 l3 = __float2bfloat16_rn(h3 - __bfloat162float(a3));
                uint2 hv, lv;
                hv.x = (uint32_t)__bfloat16_as_ushort(a1) << 16 | __bfloat16_as_ushort(a0);
                hv.y = (uint32_t)__bfloat16_as_ushort(a3) << 16 | __bfloat16_as_ushort(a2);
                lv.x = (uint32_t)__bfloat16_as_ushort(l1) << 16 | __bfloat16_as_ushort(l0);
                lv.y = (uint32_t)__bfloat16_as_ushort(l3) << 16 | __bfloat16_as_ushort(l2);
                uint32_t off = (uint32_t)m * A_STRIDE + kkl * 2;
                *(uint2*)(pAhi + off) = hv;
                *(uint2*)(pAlo + off) = lv;
            }
        }
        __syncthreads();

        // -------- GEMM: warp m16 x d32, 16 k-steps, bf16x3 --------
        float acc[4][4];
#pragma unroll
        for (int t = 0; t < 4; t++)
#pragma unroll
            for (int i = 0; i < 4; i++) acc[t][i] = 0.f;
#pragma unroll 4
        for (int ks = 0; ks < 16; ks++) {
            uint32_t koff = (uint32_t)ks * 32;
            uint32_t ah[4], al[4], bh[8], bl[8];
            ldsm_x4(ah, smAhi + aRowOff + koff);
            ldsm_x4(al, smAlo + aRowOff + koff);
            ldsm_x4(bh,     smBhi + bRowOff0 + koff);
            ldsm_x4(bh + 4, smBhi + bRowOff1 + koff);
            ldsm_x4(bl,     smBlo + bRowOff0 + koff);
            ldsm_x4(bl + 4, smBlo + bRowOff1 + koff);
#pragma unroll
            for (int t = 0; t < 4; t++) {
                mma_bf16(acc[t], ah, bh[t * 2], bh[t * 2 + 1]);   // hi*hi
                mma_bf16(acc[t], ah, bl[t * 2], bl[t * 2 + 1]);   // hi*lo
                mma_bf16(acc[t], al, bh[t * 2], bh[t * 2 + 1]);   // lo*hi
            }
        }
        __syncthreads();                       // A tiles fully read -> Es may alias Ahi

        // -------- Epilogue: bias, emb writes, Es[m][d] stash --------
        {
            int mlo = m0w + (lane >> 2);
            int mhi = mlo + 8;
            bool vlo = mlo < nv, vhi = mhi < nv;
#pragma unroll
            for (int t = 0; t < 4; t++) {
                int d = d0w + t * 8 + (lane & 3) * 2;
                float bx = b2s[d], by = b2s[d + 1];
                float e0 = acc[t][0] + bx, e1 = acc[t][1] + by;
                float e2 = acc[t][2] + bx, e3 = acc[t][3] + by;
                if (vlo) *(float2*)&out_emb[(jb + mlo) * 64 + d] = make_float2(e0, e1);
                if (vhi) *(float2*)&out_emb[(jb + mhi) * 64 + d] = make_float2(e2, e3);
                *(float2*)&Es[mlo * ES_S + d] = make_float2(e0, e1);
                *(float2*)&Es[mhi * ES_S + d] = make_float2(e2, e3);
            }
        }
        __syncthreads();

        // -------- Phase 3: branch norms (warp w -> pairs w*8..w*8+7) --------
        const float* embk = embg + (size_t)k * Tdim * Ddim;
#pragma unroll
        for (int q = 0; q < 8; q++) {
            int m  = w * 8 + q;
            int a1i = i1s[m], a2i = i2s[m];
            float e0 = Es[m * ES_S + lane];
            float e1 = Es[m * ES_S + lane + 32];
            float x0 = embk[a1i * 64 + lane]      - e0;
            float x1 = embk[a1i * 64 + lane + 32] - e1;
            float y0 = embk[a2i * 64 + lane]      - e0;
            float y1 = embk[a2i * 64 + lane + 32] - e1;
            float s1 = x0 * x0 + x1 * x1;
            float s2 = y0 * y0 + y1 * y1;
#pragma unroll
            for (int off = 16; off; off >>= 1) {
                s1 += __shfl_xor_sync(0xffffffff, s1, off);
                s2 += __shfl_xor_sync(0xffffffff, s2, off);
            }
            if (lane == 0 && m < nv) {
                out[2ull * KJ + jb + m] = sqrtf(s1);
                out[3ull * KJ + jb + m] = sqrtf(s2);
            }
        }
    }
}

// ---------------------------------------------------------------------------
extern "C" void kernel_launch(void* const* d_in, const int* in_sizes, int n_in,
                              void* d_out, int out_size) {
    const float *emb = 0, *W1 = 0, *b1 = 0, *W2 = 0, *b2 = 0;
    for (int i = 0; i < n_in; i++) {
        int s = in_sizes[i];
        if      (s == Kdim * Tdim * Ddim) emb = (const float*)d_in[i];
        else if (s == 2 * Ddim * Hdim)    W1  = (const float*)d_in[i];
        else if (s == Hdim)               b1  = (const float*)d_in[i];
        else if (s == Ddim)               b2  = (const float*)d_in[i];
        else if (s == Hdim * Ddim)        W2  = (const float*)d_in[i];  // last wins (hashes also 16384)
    }
    float* out = (float*)d_out;

    pq_kernel<<<(Kdim * Tdim) / 16, 256>>>(emb, W1, b1);

    cudaFuncSetAttribute(main_kernel, cudaFuncAttributeMaxDynamicSharedMemorySize, SMEM_BYTES);
    main_kernel<<<GRID_MAIN, NTHR, SMEM_BYTES>>>(emb, W2, b2, out);
}